// round 15
// baseline (speedup 1.0000x reference)
#include <cuda_runtime.h>
#include <math.h>

#define NN 4096
#define AA 512
#define CC 100
#define PADT 5600   // >= NN + 15*CC, multiple of 32
#define KC 16       // k-chunk
#define SROW 20     // k_cov smem row stride (floats): conflict-free fragment reads
#define NCB (PADT / 32)          // 175 member-tiles
#define CENT_BLKS (2 * NCB)      // 350
#define LOSS_BLKS (NN / 8)       // 512
#define AVO_BLKS  ((CC * AA + 255) / 256 + 1)  // 201

// Round fp32 -> tf32 (round-to-nearest-away)
__device__ __forceinline__ float tf32r(float x) {
    unsigned u;
    asm("cvt.rna.tf32.f32 %0, %1;" : "=r"(u) : "f"(x));
    return __uint_as_float(u);
}
__device__ __forceinline__ void cpa16(unsigned s, const void* gmem) {
    asm volatile("cp.async.cg.shared.global [%0], [%1], 16;" :: "r"(s), "l"(gmem));
}
#define CPCOMMIT() asm volatile("cp.async.commit_group;")
#define CPWAIT1()  asm volatile("cp.async.wait_group 1;" ::: "memory")
#define CPWAIT0()  asm volatile("cp.async.wait_group 0;" ::: "memory")

// ---------------- scratch ----------------
__device__ float g_counts[CC];
__device__ float g_w[CC];
__device__ int   g_off[CC + 1];
__device__ int   g_offp[CC + 1];
__device__ int   g_idx[NN];
__device__ float g_ave[CC * AA];
__device__ float g_rowloss[NN];
__device__ float g_centT[(size_t)AA * PADT];  // feature-major (K = member dim)

// ---------------- K1: histogram + offsets + weights ----------------
__global__ void k_hist(const int* __restrict__ labels,
                       const float* __restrict__ amount) {
    __shared__ int sc[CC];
    int tid = threadIdx.x;
    for (int i = tid; i < CC; i += blockDim.x) sc[i] = 0;
    __syncthreads();
    for (int n = tid; n < NN; n += blockDim.x)
        atomicAdd(&sc[labels[n]], 1);
    __syncthreads();
    if (tid == 0) {
        int off = 0, offp = 0;
        for (int c = 0; c < CC; c++) {
            g_off[c] = off;  g_offp[c] = offp;
            off += sc[c];    offp += (sc[c] + KC - 1) & ~(KC - 1);
        }
        g_off[CC] = off; g_offp[CC] = offp;
    }
    if (tid < CC) {
        float cnt = (float)sc[tid];
        g_counts[tid] = cnt;
        float den = cnt + amount[tid];
        g_w[tid] = (den > 0.f) ? (cnt / den) : 0.f;
    }
}

// ---------------- K2: stable member lists (warp per class, parallel) ----------------
__global__ void k_build(const int* __restrict__ labels) {
    int w = (blockIdx.x * blockDim.x + threadIdx.x) >> 5;
    int lane = threadIdx.x & 31;
    if (w >= CC) return;
    int base = g_off[w];
    for (int n0 = 0; n0 < NN; n0 += 32) {
        int n = n0 + lane;
        int match = (labels[n] == w);
        unsigned mask = __ballot_sync(0xffffffffu, (unsigned)match);
        if (match) {
            int r = __popc(mask & ((1u << lane) - 1u));
            g_idx[base + r] = n;
        }
        base += __popc(mask);
    }
}

// ---------------- K3: per-class mean (TF32-rounded, fp32 acc, MLP-4 unroll) --------
__global__ void k_ave(const float* __restrict__ f) {
    int c = blockIdx.x;
    int col = blockIdx.y * 256 + threadIdx.x;
    int base = g_off[c];
    int cnt = g_off[c + 1] - base;
    float s0 = 0.f;
    int m = 0;
    for (; m + 4 <= cnt; m += 4) {
        int n0 = g_idx[base + m];
        int n1 = g_idx[base + m + 1];
        int n2 = g_idx[base + m + 2];
        int n3 = g_idx[base + m + 3];
        float v0 = f[n0 * AA + col];
        float v1 = f[n1 * AA + col];
        float v2 = f[n2 * AA + col];
        float v3 = f[n3 * AA + col];
        s0 += tf32r(v0); s0 += tf32r(v1); s0 += tf32r(v2); s0 += tf32r(v3);
    }
    for (; m < cnt; m++) {
        int n = g_idx[base + m];
        s0 += tf32r(f[n * AA + col]);
    }
    float cs = (cnt > 0) ? (float)cnt : 1.f;
    g_ave[c * AA + col] = s0 / cs;
}

// ---------------- K3b (fused): centerT (identity order, warp-remapped) | loss | avout
__global__ void k_mix(const float* __restrict__ f,
                      const float* __restrict__ ys,
                      const int* __restrict__ labels,
                      const float* __restrict__ ave_old,
                      const float* __restrict__ amount_old,
                      float* __restrict__ out_ave,
                      float* __restrict__ out_amt) {
    int b = blockIdx.x;
    int t = threadIdx.x;

    if (b < CENT_BLKS) {
        __shared__ float tile[32][260];
        __shared__ int s_cls[32], s_n[32];
        int mt = b >> 1, half = b & 1;
        int row0 = mt * 32, a0 = half * 256;
        if (t < 32) {
            int mg = row0 + t;
            int lo = 0, hi = CC - 1;
            while (lo < hi) {
                int mid = (lo + hi + 1) >> 1;
                if (g_offp[mid] <= mg) lo = mid; else hi = mid - 1;
            }
            int c = lo;
            int mloc = mg - g_offp[c];
            int cnt = g_off[c + 1] - g_off[c];
            s_cls[t] = c;
            s_n[t] = (mloc < cnt) ? g_idx[g_off[c] + mloc] : -1;
        }
        __syncthreads();
        // phase 1: member-major coalesced read + center + tf32
        for (int e = t; e < 32 * 64; e += 256) {
            int m = e >> 6, q = e & 63;
            int n = s_n[m];
            float4 v = make_float4(0.f, 0.f, 0.f, 0.f);
            if (n >= 0) {
                float4 src = *(const float4*)(f + (size_t)n * AA + a0 + q * 4);
                const float* av = g_ave + s_cls[m] * AA + a0 + q * 4;
                v.x = tf32r(src.x - av[0]);
                v.y = tf32r(src.y - av[1]);
                v.z = tf32r(src.z - av[2]);
                v.w = tf32r(src.w - av[3]);
            }
            *(float4*)&tile[m][q * 4] = v;
        }
        __syncthreads();
        // phase 2: warp = 16 features x 2 member-quads -> conflict-free column reads
        for (int e = t; e < 256 * 8; e += 256) {
            int wi = e >> 5, lane = e & 31;
            int a  = (wi & 15) * 16 + (lane & 15);
            int mq = (wi >> 4) * 2 + (lane >> 4);
            float4 w;
            w.x = tile[mq * 4 + 0][a];
            w.y = tile[mq * 4 + 1][a];
            w.z = tile[mq * 4 + 2][a];
            w.w = tile[mq * 4 + 3][a];
            *(float4*)(g_centT + (size_t)(a0 + a) * PADT + row0 + mq * 4) = w;
        }
    } else if (b < CENT_BLKS + LOSS_BLKS) {
        // ---- per-row NLL (warp per row) ----
        int row = (b - CENT_BLKS) * 8 + (t >> 5);
        int lane = t & 31;
        const float* r = ys + (size_t)row * CC;
        float v0 = r[lane];
        float v1 = r[lane + 32];
        float v2 = r[lane + 64];
        float v3 = (lane < 4) ? r[lane + 96] : -INFINITY;
        float mx = fmaxf(fmaxf(v0, v1), fmaxf(v2, v3));
#pragma unroll
        for (int o = 16; o > 0; o >>= 1)
            mx = fmaxf(mx, __shfl_xor_sync(0xffffffffu, mx, o));
        float s = expf(v0 - mx) + expf(v1 - mx) + expf(v2 - mx)
                + ((lane < 4) ? expf(v3 - mx) : 0.f);
#pragma unroll
        for (int o = 16; o > 0; o >>= 1)
            s += __shfl_xor_sync(0xffffffffu, s, o);
        if (lane == 0) {
            int lab = labels[row];
            g_rowloss[row] = (mx + logf(s)) - r[lab];
        }
    } else {
        // ---- new_ave, new_amount ----
        int i = (b - CENT_BLKS - LOSS_BLKS) * 256 + t;
        if (i < CC * AA) {
            int c = i / AA;
            float wv = g_w[c];
            out_ave[i] = ave_old[i] * (1.f - wv) + g_ave[i] * wv;
        }
        if (i < CC) out_amt[i] = amount_old[i] + g_counts[i];
    }
}

// ---------------- K4: 64x128 tile, tf32 mma.sync, dbl-buffered, fused epilogue --------
__global__ __launch_bounds__(256, 3)
void k_cov(const float* __restrict__ cov_old,
           const float* __restrict__ ave_old,
           float* __restrict__ out_cov) {
    __shared__ float sA[2][64 * SROW];
    __shared__ float sB[2][128 * SROW];
    __shared__ float s_db[128];
    __shared__ float s_cd[64];

    int c  = blockIdx.z;
    int bi = blockIdx.y;    // 0..7, 64 rows each
    int bj = blockIdx.x;    // 0..3, 128 cols each
    int tid = threadIdx.x;
    int w = tid >> 5, lane = tid & 31;
    int wm = w >> 2, wn = w & 3;        // warp tile origin (wm*32, wn*32)
    int g = lane >> 2, tig = lane & 3;

    unsigned sA_u = (unsigned)__cvta_generic_to_shared(sA);
    unsigned sB_u = (unsigned)__cvta_generic_to_shared(sB);

    int base = g_offp[c];
    int cntp = g_offp[c + 1] - base;    // multiple of 16
    int cnt  = g_off[c + 1] - g_off[c];
    int nch  = cntp / KC;

    if (tid < 128) {
        int colg = c * AA + bj * 128 + tid;
        s_db[tid] = ave_old[colg] - g_ave[colg];
    } else if (tid < 192) {
        int t = tid - 128;
        int rowg = c * AA + bi * 64 + t;
        float wv = g_w[c];
        s_cd[t] = (wv * (1.f - wv)) * (ave_old[rowg] - g_ave[rowg]);
    }

    float acc[2][4][4];
#pragma unroll
    for (int mi = 0; mi < 2; mi++)
#pragma unroll
        for (int ni = 0; ni < 4; ni++)
#pragma unroll
            for (int q = 0; q < 4; q++) acc[mi][ni][q] = 0.f;

    auto stage = [&](int buf, int k0) {
        {
            int e = tid;            // 256 = 64 rows x 4 quads
            int r = e >> 2, q = e & 3;
            unsigned dst = (unsigned)((buf * 64 * SROW + r * SROW + q * 4) * 4);
            const float* srcA = g_centT + (size_t)(bi * 64 + r) * PADT + base + k0 + q * 4;
            cpa16(sA_u + dst, srcA);
        }
#pragma unroll
        for (int h = 0; h < 2; h++) {
            int e = tid + h * 256;  // 512 = 128 rows x 4 quads
            int r = e >> 2, q = e & 3;
            unsigned dst = (unsigned)((buf * 128 * SROW + r * SROW + q * 4) * 4);
            const float* srcB = g_centT + (size_t)(bj * 128 + r) * PADT + base + k0 + q * 4;
            cpa16(sB_u + dst, srcB);
        }
    };

    if (nch > 0) { stage(0, 0); CPCOMMIT(); }
    for (int ch = 0; ch < nch; ch++) {
        int cur = ch & 1;
        if (ch + 1 < nch) { stage(cur ^ 1, (ch + 1) * KC); CPCOMMIT(); CPWAIT1(); }
        else              { CPWAIT0(); }
        __syncthreads();
        const float* A = sA[cur];
        const float* B = sB[cur];
#pragma unroll
        for (int ks = 0; ks < 2; ks++) {
            int kk = ks * 8;
            unsigned a[2][4], b[4][2];
#pragma unroll
            for (int mi = 0; mi < 2; mi++) {
                int r0 = wm * 32 + mi * 16;
                a[mi][0] = __float_as_uint(A[(r0 + g)     * SROW + kk + tig]);
                a[mi][1] = __float_as_uint(A[(r0 + g + 8) * SROW + kk + tig]);
                a[mi][2] = __float_as_uint(A[(r0 + g)     * SROW + kk + tig + 4]);
                a[mi][3] = __float_as_uint(A[(r0 + g + 8) * SROW + kk + tig + 4]);
            }
#pragma unroll
            for (int ni = 0; ni < 4; ni++) {
                int rn = wn * 32 + ni * 8;
                b[ni][0] = __float_as_uint(B[(rn + g) * SROW + kk + tig]);
                b[ni][1] = __float_as_uint(B[(rn + g) * SROW + kk + tig + 4]);
            }
#pragma unroll
            for (int mi = 0; mi < 2; mi++)
#pragma unroll
                for (int ni = 0; ni < 4; ni++) {
                    asm volatile(
                        "mma.sync.aligned.m16n8k8.row.col.f32.tf32.tf32.f32 "
                        "{%0,%1,%2,%3}, {%4,%5,%6,%7}, {%8,%9}, {%0,%1,%2,%3};"
                        : "+f"(acc[mi][ni][0]), "+f"(acc[mi][ni][1]),
                          "+f"(acc[mi][ni][2]), "+f"(acc[mi][ni][3])
                        : "r"(a[mi][0]), "r"(a[mi][1]), "r"(a[mi][2]), "r"(a[mi][3]),
                          "r"(b[ni][0]), "r"(b[ni][1]));
                }
        }
        __syncthreads();
    }

    __syncthreads();
    float wv  = g_w[c];
    float om  = 1.f - wv;
    float cs  = (cnt > 0) ? (float)cnt : 1.f;
    float inv = wv / cs;
    size_t cbase = (size_t)c * AA * AA;

    if (om == 0.f) {
        // cov_old contribution is exactly zero -> skip the 105MB read stream
#pragma unroll
        for (int mi = 0; mi < 2; mi++) {
            int rl0 = wm * 32 + mi * 16 + g;
#pragma unroll
            for (int ni = 0; ni < 4; ni++) {
                int cl = wn * 32 + ni * 8 + tig * 2;
                size_t r1 = cbase + (size_t)(bi * 64 + rl0) * AA + bj * 128 + cl;
                size_t r2 = cbase + (size_t)(bi * 64 + rl0 + 8) * AA + bj * 128 + cl;
                float cd1 = s_cd[rl0], cd2 = s_cd[rl0 + 8];
                float db0 = s_db[cl], db1 = s_db[cl + 1];
                out_cov[r1]     = acc[mi][ni][0] * inv + cd1 * db0;
                out_cov[r1 + 1] = acc[mi][ni][1] * inv + cd1 * db1;
                out_cov[r2]     = acc[mi][ni][2] * inv + cd2 * db0;
                out_cov[r2 + 1] = acc[mi][ni][3] * inv + cd2 * db1;
            }
        }
    } else {
#pragma unroll
        for (int mi = 0; mi < 2; mi++) {
            int rl0 = wm * 32 + mi * 16 + g;
#pragma unroll
            for (int ni = 0; ni < 4; ni++) {
                int cl = wn * 32 + ni * 8 + tig * 2;
                size_t r1 = cbase + (size_t)(bi * 64 + rl0) * AA + bj * 128 + cl;
                size_t r2 = cbase + (size_t)(bi * 64 + rl0 + 8) * AA + bj * 128 + cl;
                float2 co1 = *(const float2*)(cov_old + r1);
                float2 co2 = *(const float2*)(cov_old + r2);
                float cd1 = s_cd[rl0], cd2 = s_cd[rl0 + 8];
                float db0 = s_db[cl], db1 = s_db[cl + 1];
                out_cov[r1]     = co1.x * om + acc[mi][ni][0] * inv + cd1 * db0;
                out_cov[r1 + 1] = co1.y * om + acc[mi][ni][1] * inv + cd1 * db1;
                out_cov[r2]     = co2.x * om + acc[mi][ni][2] * inv + cd2 * db0;
                out_cov[r2 + 1] = co2.y * om + acc[mi][ni][3] * inv + cd2 * db1;
            }
        }
    }
}

// ---------------- K7: deterministic tree reduce ----------------
__global__ void k_red(float* __restrict__ out_loss) {
    __shared__ float s[1024];
    int t = threadIdx.x;
    s[t] = g_rowloss[t] + g_rowloss[t + 1024] + g_rowloss[t + 2048] + g_rowloss[t + 3072];
    __syncthreads();
    for (int st = 512; st > 0; st >>= 1) {
        if (t < st) s[t] += s[t + st];
        __syncthreads();
    }
    if (t == 0) out_loss[0] = s[0] / (float)NN;
}

// ---------------- launcher ----------------
extern "C" void kernel_launch(void* const* d_in, const int* in_sizes, int n_in,
                              void* d_out, int out_size) {
    const float* features = (const float*)d_in[0];
    const float* y_s      = (const float*)d_in[1];
    const float* cov_old  = (const float*)d_in[2];
    const float* ave_old  = (const float*)d_in[3];
    const float* amount   = (const float*)d_in[4];
    const int*   labels   = (const int*)d_in[5];

    float* out      = (float*)d_out;
    float* out_loss = out;
    float* out_cov  = out + 1;
    float* out_ave  = out + 1 + (size_t)CC * AA * AA;
    float* out_amt  = out_ave + (size_t)CC * AA;

    k_hist<<<1, 256>>>(labels, amount);
    k_build<<<(CC * 32 + 255) / 256, 256>>>(labels);
    dim3 gave(CC, 2);
    k_ave<<<gave, 256>>>(features);
    k_mix<<<CENT_BLKS + LOSS_BLKS + AVO_BLKS, 256>>>(features, y_s, labels,
                                                     ave_old, amount, out_ave, out_amt);
    dim3 gcov(4, 8, CC);
    k_cov<<<gcov, 256>>>(cov_old, ave_old, out_cov);
    k_red<<<1, 1024>>>(out_loss);
}

// round 16
// speedup vs baseline: 1.0897x; 1.0897x over previous
#include <cuda_runtime.h>
#include <math.h>

#define NN 4096
#define AA 512
#define CC 100
#define PADT 5600   // >= NN + 15*CC, multiple of 32
#define KC 16       // k-chunk
#define SROW 20     // k_cov smem row stride (floats): conflict-free fragment reads
#define NCB (PADT / 32)          // 175 member-tiles
#define CENT_BLKS (2 * NCB)      // 350
#define LOSS_BLKS (NN / 8)       // 512
#define AVO_BLKS  ((CC * AA + 255) / 256 + 1)  // 201

// Round fp32 -> tf32 (round-to-nearest-away)
__device__ __forceinline__ float tf32r(float x) {
    unsigned u;
    asm("cvt.rna.tf32.f32 %0, %1;" : "=r"(u) : "f"(x));
    return __uint_as_float(u);
}
__device__ __forceinline__ void cpa16(unsigned s, const void* gmem) {
    asm volatile("cp.async.cg.shared.global [%0], [%1], 16;" :: "r"(s), "l"(gmem));
}
#define CPCOMMIT() asm volatile("cp.async.commit_group;")
#define CPWAIT1()  asm volatile("cp.async.wait_group 1;" ::: "memory")
#define CPWAIT0()  asm volatile("cp.async.wait_group 0;" ::: "memory")

// ---------------- scratch ----------------
__device__ float g_counts[CC];
__device__ float g_w[CC];
__device__ int   g_off[CC + 1];
__device__ int   g_offp[CC + 1];
__device__ int   g_idx[NN];
__device__ float g_ave[CC * AA];
__device__ float g_rowloss[NN];
__device__ float g_centT[(size_t)AA * PADT];  // feature-major (K = member dim)

// ---------------- K1 (fused): per-class hist + offsets + list + mean -------------
// block per class; redundant smem histogram per block (cheap, removes serialization)
__global__ void k_prep(const int* __restrict__ labels,
                       const float* __restrict__ amount,
                       const float* __restrict__ f) {
    __shared__ int sc[CC];
    __shared__ int wcnt[8];
    __shared__ int s_off, s_cnt;
    int c = blockIdx.x;
    int tid = threadIdx.x;
    int w = tid >> 5, lane = tid & 31;

    for (int i = tid; i < CC; i += 256) sc[i] = 0;
    __syncthreads();
    for (int n = tid; n < NN; n += 256)
        atomicAdd(&sc[labels[n]], 1);
    __syncthreads();

    if (tid == 0) {
        int off = 0, offp = 0;
        for (int i = 0; i < c; i++) {
            off += sc[i];
            offp += (sc[i] + KC - 1) & ~(KC - 1);
        }
        s_off = off; s_cnt = sc[c];
        g_off[c] = off; g_offp[c] = offp;
        float cnt = (float)sc[c];
        g_counts[c] = cnt;
        float den = cnt + amount[c];
        g_w[c] = (den > 0.f) ? (cnt / den) : 0.f;
        if (c == 0) {
            int offT = 0, offpT = 0;
            for (int i = 0; i < CC; i++) {
                offT += sc[i];
                offpT += (sc[i] + KC - 1) & ~(KC - 1);
            }
            g_off[CC] = offT; g_offp[CC] = offpT;
        }
    }
    __syncthreads();

    // stable member list: warp w covers n in [512w, 512w+512)
    int cw = 0;
    for (int n0 = w * 512; n0 < w * 512 + 512; n0 += 32) {
        int match = (labels[n0 + lane] == c);
        cw += __popc(__ballot_sync(0xffffffffu, (unsigned)match));
    }
    if (lane == 0) wcnt[w] = cw;
    __syncthreads();
    int base = s_off;
    for (int i = 0; i < w; i++) base += wcnt[i];
    for (int n0 = w * 512; n0 < w * 512 + 512; n0 += 32) {
        int n = n0 + lane;
        int match = (labels[n] == c);
        unsigned mask = __ballot_sync(0xffffffffu, (unsigned)match);
        if (match) {
            int r = __popc(mask & ((1u << lane) - 1u));
            g_idx[base + r] = n;
        }
        base += __popc(mask);
    }
    __syncthreads();

    // per-class mean (TF32-rounded, fp32 acc, MLP-4, sequential add order)
    int off = s_off, cnt = s_cnt;
    float s0 = 0.f, s1 = 0.f;
    int m = 0;
    for (; m + 4 <= cnt; m += 4) {
        int n0 = g_idx[off + m];
        int n1 = g_idx[off + m + 1];
        int n2 = g_idx[off + m + 2];
        int n3 = g_idx[off + m + 3];
        float a0 = f[n0 * AA + tid],       b0 = f[n0 * AA + 256 + tid];
        float a1 = f[n1 * AA + tid],       b1 = f[n1 * AA + 256 + tid];
        float a2 = f[n2 * AA + tid],       b2 = f[n2 * AA + 256 + tid];
        float a3 = f[n3 * AA + tid],       b3 = f[n3 * AA + 256 + tid];
        s0 += tf32r(a0); s0 += tf32r(a1); s0 += tf32r(a2); s0 += tf32r(a3);
        s1 += tf32r(b0); s1 += tf32r(b1); s1 += tf32r(b2); s1 += tf32r(b3);
    }
    for (; m < cnt; m++) {
        int n = g_idx[off + m];
        s0 += tf32r(f[n * AA + tid]);
        s1 += tf32r(f[n * AA + 256 + tid]);
    }
    float cs = (cnt > 0) ? (float)cnt : 1.f;
    g_ave[c * AA + tid] = s0 / cs;
    g_ave[c * AA + 256 + tid] = s1 / cs;
}

// ---------------- K2 (fused): centerT (R13 layout) | loss | avout ----------------
__global__ void k_mix(const float* __restrict__ f,
                      const float* __restrict__ ys,
                      const int* __restrict__ labels,
                      const float* __restrict__ ave_old,
                      const float* __restrict__ amount_old,
                      float* __restrict__ out_ave,
                      float* __restrict__ out_amt) {
    int b = blockIdx.x;
    int t = threadIdx.x;

    if (b < CENT_BLKS) {
        __shared__ float tile[32][260];
        __shared__ int s_cls[32], s_n[32];
        int mt = b >> 1, half = b & 1;
        int row0 = mt * 32, a0 = half * 256;
        if (t < 32) {
            int mg = row0 + t;
            int lo = 0, hi = CC - 1;
            while (lo < hi) {
                int mid = (lo + hi + 1) >> 1;
                if (g_offp[mid] <= mg) lo = mid; else hi = mid - 1;
            }
            int c = lo;
            int mloc = mg - g_offp[c];
            int cnt = g_off[c + 1] - g_off[c];
            s_cls[t] = c;
            s_n[t] = (mloc < cnt) ? g_idx[g_off[c] + mloc] : -1;
        }
        __syncthreads();
        // phase 1: member-major coalesced read + center + tf32
        for (int e = t; e < 32 * 64; e += 256) {
            int m = e >> 6, q = e & 63;
            int n = s_n[m];
            float4 v = make_float4(0.f, 0.f, 0.f, 0.f);
            if (n >= 0) {
                float4 src = *(const float4*)(f + (size_t)n * AA + a0 + q * 4);
                const float* av = g_ave + s_cls[m] * AA + a0 + q * 4;
                v.x = tf32r(src.x - av[0]);
                v.y = tf32r(src.y - av[1]);
                v.z = tf32r(src.z - av[2]);
                v.w = tf32r(src.w - av[3]);
            }
            *(float4*)&tile[m][q * 4] = v;
        }
        __syncthreads();
        // phase 2 (R13 layout): coalesced 128B gmem writes per feature row
        for (int e = t; e < 256 * 8; e += 256) {
            int a = e >> 3, mq = e & 7;
            float4 w;
            w.x = tile[mq * 4 + 0][a];
            w.y = tile[mq * 4 + 1][a];
            w.z = tile[mq * 4 + 2][a];
            w.w = tile[mq * 4 + 3][a];
            *(float4*)(g_centT + (size_t)(a0 + a) * PADT + row0 + mq * 4) = w;
        }
    } else if (b < CENT_BLKS + LOSS_BLKS) {
        // ---- per-row NLL (warp per row) ----
        int row = (b - CENT_BLKS) * 8 + (t >> 5);
        int lane = t & 31;
        const float* r = ys + (size_t)row * CC;
        float v0 = r[lane];
        float v1 = r[lane + 32];
        float v2 = r[lane + 64];
        float v3 = (lane < 4) ? r[lane + 96] : -INFINITY;
        float mx = fmaxf(fmaxf(v0, v1), fmaxf(v2, v3));
#pragma unroll
        for (int o = 16; o > 0; o >>= 1)
            mx = fmaxf(mx, __shfl_xor_sync(0xffffffffu, mx, o));
        float s = expf(v0 - mx) + expf(v1 - mx) + expf(v2 - mx)
                + ((lane < 4) ? expf(v3 - mx) : 0.f);
#pragma unroll
        for (int o = 16; o > 0; o >>= 1)
            s += __shfl_xor_sync(0xffffffffu, s, o);
        if (lane == 0) {
            int lab = labels[row];
            g_rowloss[row] = (mx + logf(s)) - r[lab];
        }
    } else {
        // ---- new_ave, new_amount ----
        int i = (b - CENT_BLKS - LOSS_BLKS) * 256 + t;
        if (i < CC * AA) {
            int c = i / AA;
            float wv = g_w[c];
            out_ave[i] = ave_old[i] * (1.f - wv) + g_ave[i] * wv;
        }
        if (i < CC) out_amt[i] = amount_old[i] + g_counts[i];
    }
}

// ---------------- K3: 64x128 tile, tf32 mma.sync, dbl-buffered, fused epilogue --------
__global__ __launch_bounds__(256, 3)
void k_cov(const float* __restrict__ cov_old,
           const float* __restrict__ ave_old,
           float* __restrict__ out_cov) {
    __shared__ float sA[2][64 * SROW];
    __shared__ float sB[2][128 * SROW];
    __shared__ float s_db[128];
    __shared__ float s_cd[64];

    int c  = blockIdx.z;
    int bi = blockIdx.y;    // 0..7, 64 rows each
    int bj = blockIdx.x;    // 0..3, 128 cols each
    int tid = threadIdx.x;
    int w = tid >> 5, lane = tid & 31;
    int wm = w >> 2, wn = w & 3;        // warp tile origin (wm*32, wn*32)
    int g = lane >> 2, tig = lane & 3;

    unsigned sA_u = (unsigned)__cvta_generic_to_shared(sA);
    unsigned sB_u = (unsigned)__cvta_generic_to_shared(sB);

    int base = g_offp[c];
    int cntp = g_offp[c + 1] - base;    // multiple of 16
    int cnt  = g_off[c + 1] - g_off[c];
    int nch  = cntp / KC;

    if (tid < 128) {
        int colg = c * AA + bj * 128 + tid;
        s_db[tid] = ave_old[colg] - g_ave[colg];
    } else if (tid < 192) {
        int t = tid - 128;
        int rowg = c * AA + bi * 64 + t;
        float wv = g_w[c];
        s_cd[t] = (wv * (1.f - wv)) * (ave_old[rowg] - g_ave[rowg]);
    }

    float acc[2][4][4];
#pragma unroll
    for (int mi = 0; mi < 2; mi++)
#pragma unroll
        for (int ni = 0; ni < 4; ni++)
#pragma unroll
            for (int q = 0; q < 4; q++) acc[mi][ni][q] = 0.f;

    auto stage = [&](int buf, int k0) {
        {
            int e = tid;            // 256 = 64 rows x 4 quads
            int r = e >> 2, q = e & 3;
            unsigned dst = (unsigned)((buf * 64 * SROW + r * SROW + q * 4) * 4);
            const float* srcA = g_centT + (size_t)(bi * 64 + r) * PADT + base + k0 + q * 4;
            cpa16(sA_u + dst, srcA);
        }
#pragma unroll
        for (int h = 0; h < 2; h++) {
            int e = tid + h * 256;  // 512 = 128 rows x 4 quads
            int r = e >> 2, q = e & 3;
            unsigned dst = (unsigned)((buf * 128 * SROW + r * SROW + q * 4) * 4);
            const float* srcB = g_centT + (size_t)(bj * 128 + r) * PADT + base + k0 + q * 4;
            cpa16(sB_u + dst, srcB);
        }
    };

    if (nch > 0) { stage(0, 0); CPCOMMIT(); }
    for (int ch = 0; ch < nch; ch++) {
        int cur = ch & 1;
        if (ch + 1 < nch) { stage(cur ^ 1, (ch + 1) * KC); CPCOMMIT(); CPWAIT1(); }
        else              { CPWAIT0(); }
        __syncthreads();
        const float* A = sA[cur];
        const float* B = sB[cur];
#pragma unroll
        for (int ks = 0; ks < 2; ks++) {
            int kk = ks * 8;
            unsigned a[2][4], b[4][2];
#pragma unroll
            for (int mi = 0; mi < 2; mi++) {
                int r0 = wm * 32 + mi * 16;
                a[mi][0] = __float_as_uint(A[(r0 + g)     * SROW + kk + tig]);
                a[mi][1] = __float_as_uint(A[(r0 + g + 8) * SROW + kk + tig]);
                a[mi][2] = __float_as_uint(A[(r0 + g)     * SROW + kk + tig + 4]);
                a[mi][3] = __float_as_uint(A[(r0 + g + 8) * SROW + kk + tig + 4]);
            }
#pragma unroll
            for (int ni = 0; ni < 4; ni++) {
                int rn = wn * 32 + ni * 8;
                b[ni][0] = __float_as_uint(B[(rn + g) * SROW + kk + tig]);
                b[ni][1] = __float_as_uint(B[(rn + g) * SROW + kk + tig + 4]);
            }
#pragma unroll
            for (int mi = 0; mi < 2; mi++)
#pragma unroll
                for (int ni = 0; ni < 4; ni++) {
                    asm volatile(
                        "mma.sync.aligned.m16n8k8.row.col.f32.tf32.tf32.f32 "
                        "{%0,%1,%2,%3}, {%4,%5,%6,%7}, {%8,%9}, {%0,%1,%2,%3};"
                        : "+f"(acc[mi][ni][0]), "+f"(acc[mi][ni][1]),
                          "+f"(acc[mi][ni][2]), "+f"(acc[mi][ni][3])
                        : "r"(a[mi][0]), "r"(a[mi][1]), "r"(a[mi][2]), "r"(a[mi][3]),
                          "r"(b[ni][0]), "r"(b[ni][1]));
                }
        }
        __syncthreads();
    }

    __syncthreads();
    float wv  = g_w[c];
    float om  = 1.f - wv;
    float cs  = (cnt > 0) ? (float)cnt : 1.f;
    float inv = wv / cs;
    size_t cbase = (size_t)c * AA * AA;

    if (om == 0.f) {
        // cov_old contribution is exactly zero -> skip the 105MB read stream
#pragma unroll
        for (int mi = 0; mi < 2; mi++) {
            int rl0 = wm * 32 + mi * 16 + g;
#pragma unroll
            for (int ni = 0; ni < 4; ni++) {
                int cl = wn * 32 + ni * 8 + tig * 2;
                size_t r1 = cbase + (size_t)(bi * 64 + rl0) * AA + bj * 128 + cl;
                size_t r2 = cbase + (size_t)(bi * 64 + rl0 + 8) * AA + bj * 128 + cl;
                float cd1 = s_cd[rl0], cd2 = s_cd[rl0 + 8];
                float db0 = s_db[cl], db1 = s_db[cl + 1];
                out_cov[r1]     = acc[mi][ni][0] * inv + cd1 * db0;
                out_cov[r1 + 1] = acc[mi][ni][1] * inv + cd1 * db1;
                out_cov[r2]     = acc[mi][ni][2] * inv + cd2 * db0;
                out_cov[r2 + 1] = acc[mi][ni][3] * inv + cd2 * db1;
            }
        }
    } else {
#pragma unroll
        for (int mi = 0; mi < 2; mi++) {
            int rl0 = wm * 32 + mi * 16 + g;
#pragma unroll
            for (int ni = 0; ni < 4; ni++) {
                int cl = wn * 32 + ni * 8 + tig * 2;
                size_t r1 = cbase + (size_t)(bi * 64 + rl0) * AA + bj * 128 + cl;
                size_t r2 = cbase + (size_t)(bi * 64 + rl0 + 8) * AA + bj * 128 + cl;
                float2 co1 = *(const float2*)(cov_old + r1);
                float2 co2 = *(const float2*)(cov_old + r2);
                float cd1 = s_cd[rl0], cd2 = s_cd[rl0 + 8];
                float db0 = s_db[cl], db1 = s_db[cl + 1];
                out_cov[r1]     = co1.x * om + acc[mi][ni][0] * inv + cd1 * db0;
                out_cov[r1 + 1] = co1.y * om + acc[mi][ni][1] * inv + cd1 * db1;
                out_cov[r2]     = co2.x * om + acc[mi][ni][2] * inv + cd2 * db0;
                out_cov[r2 + 1] = co2.y * om + acc[mi][ni][3] * inv + cd2 * db1;
            }
        }
    }
}

// ---------------- K4: deterministic tree reduce ----------------
__global__ void k_red(float* __restrict__ out_loss) {
    __shared__ float s[1024];
    int t = threadIdx.x;
    s[t] = g_rowloss[t] + g_rowloss[t + 1024] + g_rowloss[t + 2048] + g_rowloss[t + 3072];
    __syncthreads();
    for (int st = 512; st > 0; st >>= 1) {
        if (t < st) s[t] += s[t + st];
        __syncthreads();
    }
    if (t == 0) out_loss[0] = s[0] / (float)NN;
}

// ---------------- launcher ----------------
extern "C" void kernel_launch(void* const* d_in, const int* in_sizes, int n_in,
                              void* d_out, int out_size) {
    const float* features = (const float*)d_in[0];
    const float* y_s      = (const float*)d_in[1];
    const float* cov_old  = (const float*)d_in[2];
    const float* ave_old  = (const float*)d_in[3];
    const float* amount   = (const float*)d_in[4];
    const int*   labels   = (const int*)d_in[5];

    float* out      = (float*)d_out;
    float* out_loss = out;
    float* out_cov  = out + 1;
    float* out_ave  = out + 1 + (size_t)CC * AA * AA;
    float* out_amt  = out_ave + (size_t)CC * AA;

    k_prep<<<CC, 256>>>(labels, amount, features);
    k_mix<<<CENT_BLKS + LOSS_BLKS + AVO_BLKS, 256>>>(features, y_s, labels,
                                                     ave_old, amount, out_ave, out_amt);
    dim3 gcov(4, 8, CC);
    k_cov<<<gcov, 256>>>(cov_old, ave_old, out_cov);
    k_red<<<1, 1024>>>(out_loss);
}

// round 17
// speedup vs baseline: 1.1188x; 1.0266x over previous
#include <cuda_runtime.h>
#include <math.h>

#define NN 4096
#define AA 512
#define CC 100
#define PADT 5600   // >= NN + 15*CC, multiple of 32
#define KC 16       // k-chunk
#define SROW 20     // k_cov smem row stride (floats): conflict-free fragment reads
#define NCB (PADT / 32)          // 175 member-tiles
#define CENT_BLKS (2 * NCB)      // 350
#define LOSS_BLKS (NN / 8)       // 512

// Round fp32 -> tf32 (round-to-nearest-away)
__device__ __forceinline__ float tf32r(float x) {
    unsigned u;
    asm("cvt.rna.tf32.f32 %0, %1;" : "=r"(u) : "f"(x));
    return __uint_as_float(u);
}
__device__ __forceinline__ void cpa16(unsigned s, const void* gmem) {
    asm volatile("cp.async.cg.shared.global [%0], [%1], 16;" :: "r"(s), "l"(gmem));
}
#define CPCOMMIT() asm volatile("cp.async.commit_group;")
#define CPWAIT1()  asm volatile("cp.async.wait_group 1;" ::: "memory")
#define CPWAIT0()  asm volatile("cp.async.wait_group 0;" ::: "memory")

// ---------------- scratch ----------------
__device__ float g_counts[CC];
__device__ float g_w[CC];
__device__ int   g_off[CC + 1];
__device__ int   g_offp[CC + 1];
__device__ int   g_idx[NN];
__device__ float g_ave[CC * AA];
__device__ float g_rowloss[NN];
__device__ float g_centT[(size_t)AA * PADT];  // feature-major (K = member dim)

// ---------------- K1 (fused): class blocks (hist+list+mean+avout) | loss rows --------
__global__ void k_prep(const int* __restrict__ labels,
                       const float* __restrict__ amount,
                       const float* __restrict__ f,
                       const float* __restrict__ ys,
                       const float* __restrict__ ave_old,
                       float* __restrict__ out_ave,
                       float* __restrict__ out_amt) {
    int blk = blockIdx.x;
    int tid = threadIdx.x;

    if (blk >= CC) {
        // ---- per-row NLL (warp per row) ----
        int row = (blk - CC) * 8 + (tid >> 5);
        int lane = tid & 31;
        const float* r = ys + (size_t)row * CC;
        float v0 = r[lane];
        float v1 = r[lane + 32];
        float v2 = r[lane + 64];
        float v3 = (lane < 4) ? r[lane + 96] : -INFINITY;
        float mx = fmaxf(fmaxf(v0, v1), fmaxf(v2, v3));
#pragma unroll
        for (int o = 16; o > 0; o >>= 1)
            mx = fmaxf(mx, __shfl_xor_sync(0xffffffffu, mx, o));
        float s = expf(v0 - mx) + expf(v1 - mx) + expf(v2 - mx)
                + ((lane < 4) ? expf(v3 - mx) : 0.f);
#pragma unroll
        for (int o = 16; o > 0; o >>= 1)
            s += __shfl_xor_sync(0xffffffffu, s, o);
        if (lane == 0) {
            int lab = labels[row];
            g_rowloss[row] = (mx + logf(s)) - r[lab];
        }
        return;
    }

    // ---- class block ----
    __shared__ int sc[CC];
    __shared__ int wcnt[8];
    __shared__ int s_off, s_cnt;
    int c = blk;
    int w = tid >> 5, lane = tid & 31;

    for (int i = tid; i < CC; i += 256) sc[i] = 0;
    __syncthreads();
    for (int n = tid; n < NN; n += 256)
        atomicAdd(&sc[labels[n]], 1);
    __syncthreads();

    if (tid == 0) {
        int off = 0, offp = 0;
        for (int i = 0; i < c; i++) {
            off += sc[i];
            offp += (sc[i] + KC - 1) & ~(KC - 1);
        }
        s_off = off; s_cnt = sc[c];
        g_off[c] = off; g_offp[c] = offp;
        float cnt = (float)sc[c];
        g_counts[c] = cnt;
        float den = cnt + amount[c];
        float wv = (den > 0.f) ? (cnt / den) : 0.f;
        g_w[c] = wv;
        out_amt[c] = amount[c] + cnt;
        if (c == 0) {
            int offT = 0, offpT = 0;
            for (int i = 0; i < CC; i++) {
                offT += sc[i];
                offpT += (sc[i] + KC - 1) & ~(KC - 1);
            }
            g_off[CC] = offT; g_offp[CC] = offpT;
        }
    }
    __syncthreads();

    // stable member list: warp w covers n in [512w, 512w+512)
    int cw = 0;
    for (int n0 = w * 512; n0 < w * 512 + 512; n0 += 32) {
        int match = (labels[n0 + lane] == c);
        cw += __popc(__ballot_sync(0xffffffffu, (unsigned)match));
    }
    if (lane == 0) wcnt[w] = cw;
    __syncthreads();
    int base = s_off;
    for (int i = 0; i < w; i++) base += wcnt[i];
    for (int n0 = w * 512; n0 < w * 512 + 512; n0 += 32) {
        int n = n0 + lane;
        int match = (labels[n] == c);
        unsigned mask = __ballot_sync(0xffffffffu, (unsigned)match);
        if (match) {
            int r = __popc(mask & ((1u << lane) - 1u));
            g_idx[base + r] = n;
        }
        base += __popc(mask);
    }
    __syncthreads();

    // per-class mean (TF32-rounded, fp32 acc, MLP-4, sequential add order)
    int off = s_off, cnt = s_cnt;
    float s0 = 0.f, s1 = 0.f;
    int m = 0;
    for (; m + 4 <= cnt; m += 4) {
        int n0 = g_idx[off + m];
        int n1 = g_idx[off + m + 1];
        int n2 = g_idx[off + m + 2];
        int n3 = g_idx[off + m + 3];
        float a0 = f[n0 * AA + tid],       b0 = f[n0 * AA + 256 + tid];
        float a1 = f[n1 * AA + tid],       b1 = f[n1 * AA + 256 + tid];
        float a2 = f[n2 * AA + tid],       b2 = f[n2 * AA + 256 + tid];
        float a3 = f[n3 * AA + tid],       b3 = f[n3 * AA + 256 + tid];
        s0 += tf32r(a0); s0 += tf32r(a1); s0 += tf32r(a2); s0 += tf32r(a3);
        s1 += tf32r(b0); s1 += tf32r(b1); s1 += tf32r(b2); s1 += tf32r(b3);
    }
    for (; m < cnt; m++) {
        int n = g_idx[off + m];
        s0 += tf32r(f[n * AA + tid]);
        s1 += tf32r(f[n * AA + 256 + tid]);
    }
    float cs = (cnt > 0) ? (float)cnt : 1.f;
    float av0 = s0 / cs, av1 = s1 / cs;
    g_ave[c * AA + tid] = av0;
    g_ave[c * AA + 256 + tid] = av1;
    // fused avout (values straight from registers)
    float wv = g_w[c];
    out_ave[c * AA + tid]       = ave_old[c * AA + tid] * (1.f - wv) + av0 * wv;
    out_ave[c * AA + 256 + tid] = ave_old[c * AA + 256 + tid] * (1.f - wv) + av1 * wv;
}

// ---------------- K2: centerT only (R13 layout) ----------------
__global__ void k_cent(const float* __restrict__ f) {
    __shared__ float tile[32][260];
    __shared__ int s_cls[32], s_n[32];
    int b = blockIdx.x;
    int t = threadIdx.x;
    int mt = b >> 1, half = b & 1;
    int row0 = mt * 32, a0 = half * 256;
    if (t < 32) {
        int mg = row0 + t;
        int lo = 0, hi = CC - 1;
        while (lo < hi) {
            int mid = (lo + hi + 1) >> 1;
            if (g_offp[mid] <= mg) lo = mid; else hi = mid - 1;
        }
        int c = lo;
        int mloc = mg - g_offp[c];
        int cnt = g_off[c + 1] - g_off[c];
        s_cls[t] = c;
        s_n[t] = (mloc < cnt) ? g_idx[g_off[c] + mloc] : -1;
    }
    __syncthreads();
    for (int e = t; e < 32 * 64; e += 256) {
        int m = e >> 6, q = e & 63;
        int n = s_n[m];
        float4 v = make_float4(0.f, 0.f, 0.f, 0.f);
        if (n >= 0) {
            float4 src = *(const float4*)(f + (size_t)n * AA + a0 + q * 4);
            const float* av = g_ave + s_cls[m] * AA + a0 + q * 4;
            v.x = tf32r(src.x - av[0]);
            v.y = tf32r(src.y - av[1]);
            v.z = tf32r(src.z - av[2]);
            v.w = tf32r(src.w - av[3]);
        }
        *(float4*)&tile[m][q * 4] = v;
    }
    __syncthreads();
    for (int e = t; e < 256 * 8; e += 256) {
        int a = e >> 3, mq = e & 7;
        float4 w;
        w.x = tile[mq * 4 + 0][a];
        w.y = tile[mq * 4 + 1][a];
        w.z = tile[mq * 4 + 2][a];
        w.w = tile[mq * 4 + 3][a];
        *(float4*)(g_centT + (size_t)(a0 + a) * PADT + row0 + mq * 4) = w;
    }
}

// ---------------- K3: 64x128 tile tf32 mma + fused epilogue + folded loss-reduce ------
__global__ __launch_bounds__(256, 3)
void k_cov(const float* __restrict__ cov_old,
           const float* __restrict__ ave_old,
           float* __restrict__ out_cov,
           float* __restrict__ out_loss) {
    int c  = blockIdx.z;
    int bi = blockIdx.y;
    int bj = blockIdx.x;
    int tid = threadIdx.x;

    if (c == CC) {
        // folded deterministic loss reduce (one block; others exit)
        if (bi != 0 || bj != 0) return;
        __shared__ float s[256];
        float acc = 0.f;
        for (int k = 0; k < 16; k++)
            acc += g_rowloss[tid + k * 256];
        s[tid] = acc;
        __syncthreads();
        for (int st = 128; st > 0; st >>= 1) {
            if (tid < st) s[tid] += s[tid + st];
            __syncthreads();
        }
        if (tid == 0) out_loss[0] = s[0] / (float)NN;
        return;
    }

    __shared__ float sA[2][64 * SROW];
    __shared__ float sB[2][128 * SROW];
    __shared__ float s_db[128];
    __shared__ float s_cd[64];

    int w = tid >> 5, lane = tid & 31;
    int wm = w >> 2, wn = w & 3;        // warp tile origin (wm*32, wn*32)
    int g = lane >> 2, tig = lane & 3;

    unsigned sA_u = (unsigned)__cvta_generic_to_shared(sA);
    unsigned sB_u = (unsigned)__cvta_generic_to_shared(sB);

    int base = g_offp[c];
    int cntp = g_offp[c + 1] - base;    // multiple of 16
    int cnt  = g_off[c + 1] - g_off[c];
    int nch  = cntp / KC;

    if (tid < 128) {
        int colg = c * AA + bj * 128 + tid;
        s_db[tid] = ave_old[colg] - g_ave[colg];
    } else if (tid < 192) {
        int t = tid - 128;
        int rowg = c * AA + bi * 64 + t;
        float wv = g_w[c];
        s_cd[t] = (wv * (1.f - wv)) * (ave_old[rowg] - g_ave[rowg]);
    }

    float acc[2][4][4];
#pragma unroll
    for (int mi = 0; mi < 2; mi++)
#pragma unroll
        for (int ni = 0; ni < 4; ni++)
#pragma unroll
            for (int q = 0; q < 4; q++) acc[mi][ni][q] = 0.f;

    auto stage = [&](int buf, int k0) {
        {
            int e = tid;            // 256 = 64 rows x 4 quads
            int r = e >> 2, q = e & 3;
            unsigned dst = (unsigned)((buf * 64 * SROW + r * SROW + q * 4) * 4);
            const float* srcA = g_centT + (size_t)(bi * 64 + r) * PADT + base + k0 + q * 4;
            cpa16(sA_u + dst, srcA);
        }
#pragma unroll
        for (int h = 0; h < 2; h++) {
            int e = tid + h * 256;  // 512 = 128 rows x 4 quads
            int r = e >> 2, q = e & 3;
            unsigned dst = (unsigned)((buf * 128 * SROW + r * SROW + q * 4) * 4);
            const float* srcB = g_centT + (size_t)(bj * 128 + r) * PADT + base + k0 + q * 4;
            cpa16(sB_u + dst, srcB);
        }
    };

    if (nch > 0) { stage(0, 0); CPCOMMIT(); }
    for (int ch = 0; ch < nch; ch++) {
        int cur = ch & 1;
        if (ch + 1 < nch) { stage(cur ^ 1, (ch + 1) * KC); CPCOMMIT(); CPWAIT1(); }
        else              { CPWAIT0(); }
        __syncthreads();
        const float* A = sA[cur];
        const float* B = sB[cur];
#pragma unroll
        for (int ks = 0; ks < 2; ks++) {
            int kk = ks * 8;
            unsigned a[2][4], b[4][2];
#pragma unroll
            for (int mi = 0; mi < 2; mi++) {
                int r0 = wm * 32 + mi * 16;
                a[mi][0] = __float_as_uint(A[(r0 + g)     * SROW + kk + tig]);
                a[mi][1] = __float_as_uint(A[(r0 + g + 8) * SROW + kk + tig]);
                a[mi][2] = __float_as_uint(A[(r0 + g)     * SROW + kk + tig + 4]);
                a[mi][3] = __float_as_uint(A[(r0 + g + 8) * SROW + kk + tig + 4]);
            }
#pragma unroll
            for (int ni = 0; ni < 4; ni++) {
                int rn = wn * 32 + ni * 8;
                b[ni][0] = __float_as_uint(B[(rn + g) * SROW + kk + tig]);
                b[ni][1] = __float_as_uint(B[(rn + g) * SROW + kk + tig + 4]);
            }
#pragma unroll
            for (int mi = 0; mi < 2; mi++)
#pragma unroll
                for (int ni = 0; ni < 4; ni++) {
                    asm volatile(
                        "mma.sync.aligned.m16n8k8.row.col.f32.tf32.tf32.f32 "
                        "{%0,%1,%2,%3}, {%4,%5,%6,%7}, {%8,%9}, {%0,%1,%2,%3};"
                        : "+f"(acc[mi][ni][0]), "+f"(acc[mi][ni][1]),
                          "+f"(acc[mi][ni][2]), "+f"(acc[mi][ni][3])
                        : "r"(a[mi][0]), "r"(a[mi][1]), "r"(a[mi][2]), "r"(a[mi][3]),
                          "r"(b[ni][0]), "r"(b[ni][1]));
                }
        }
        __syncthreads();
    }

    __syncthreads();
    float wv  = g_w[c];
    float om  = 1.f - wv;
    float cs  = (cnt > 0) ? (float)cnt : 1.f;
    float inv = wv / cs;
    size_t cbase = (size_t)c * AA * AA;

    if (om == 0.f) {
#pragma unroll
        for (int mi = 0; mi < 2; mi++) {
            int rl0 = wm * 32 + mi * 16 + g;
#pragma unroll
            for (int ni = 0; ni < 4; ni++) {
                int cl = wn * 32 + ni * 8 + tig * 2;
                size_t r1 = cbase + (size_t)(bi * 64 + rl0) * AA + bj * 128 + cl;
                size_t r2 = cbase + (size_t)(bi * 64 + rl0 + 8) * AA + bj * 128 + cl;
                float cd1 = s_cd[rl0], cd2 = s_cd[rl0 + 8];
                float db0 = s_db[cl], db1 = s_db[cl + 1];
                out_cov[r1]     = acc[mi][ni][0] * inv + cd1 * db0;
                out_cov[r1 + 1] = acc[mi][ni][1] * inv + cd1 * db1;
                out_cov[r2]     = acc[mi][ni][2] * inv + cd2 * db0;
                out_cov[r2 + 1] = acc[mi][ni][3] * inv + cd2 * db1;
            }
        }
    } else {
#pragma unroll
        for (int mi = 0; mi < 2; mi++) {
            int rl0 = wm * 32 + mi * 16 + g;
#pragma unroll
            for (int ni = 0; ni < 4; ni++) {
                int cl = wn * 32 + ni * 8 + tig * 2;
                size_t r1 = cbase + (size_t)(bi * 64 + rl0) * AA + bj * 128 + cl;
                size_t r2 = cbase + (size_t)(bi * 64 + rl0 + 8) * AA + bj * 128 + cl;
                float2 co1 = *(const float2*)(cov_old + r1);
                float2 co2 = *(const float2*)(cov_old + r2);
                float cd1 = s_cd[rl0], cd2 = s_cd[rl0 + 8];
                float db0 = s_db[cl], db1 = s_db[cl + 1];
                out_cov[r1]     = co1.x * om + acc[mi][ni][0] * inv + cd1 * db0;
                out_cov[r1 + 1] = co1.y * om + acc[mi][ni][1] * inv + cd1 * db1;
                out_cov[r2]     = co2.x * om + acc[mi][ni][2] * inv + cd2 * db0;
                out_cov[r2 + 1] = co2.y * om + acc[mi][ni][3] * inv + cd2 * db1;
            }
        }
    }
}

// ---------------- launcher ----------------
extern "C" void kernel_launch(void* const* d_in, const int* in_sizes, int n_in,
                              void* d_out, int out_size) {
    const float* features = (const float*)d_in[0];
    const float* y_s      = (const float*)d_in[1];
    const float* cov_old  = (const float*)d_in[2];
    const float* ave_old  = (const float*)d_in[3];
    const float* amount   = (const float*)d_in[4];
    const int*   labels   = (const int*)d_in[5];

    float* out      = (float*)d_out;
    float* out_loss = out;
    float* out_cov  = out + 1;
    float* out_ave  = out + 1 + (size_t)CC * AA * AA;
    float* out_amt  = out_ave + (size_t)CC * AA;

    k_prep<<<CC + LOSS_BLKS, 256>>>(labels, amount, features, y_s,
                                    ave_old, out_ave, out_amt);
    k_cent<<<CENT_BLKS, 256>>>(features);
    dim3 gcov(4, 8, CC + 1);
    k_cov<<<gcov, 256>>>(cov_old, ave_old, out_cov, out_loss);
}